// round 1
// baseline (speedup 1.0000x reference)
#include <cuda_runtime.h>
#include <cuda_bf16.h>
#include <cstdint>

// Problem constants
#define Bz   2
#define Sq   2048
#define DIM  1024
#define Hn   16
#define DHd  64
#define INNER (Hn*DHd)          // 1024
#define TOK  (Bz*Sq)            // 4096

// Scratch (device globals — no allocation allowed)
__device__ float g_xn[TOK*DIM];
__device__ float g_q [TOK*INNER];
__device__ float g_kv[TOK*2*INNER];
__device__ float g_qh[Bz*Hn*Sq*DHd];
__device__ float g_kh[Bz*Hn*Sq*DHd];
__device__ float g_vh[Bz*Hn*Sq*DHd];
__device__ float g_ao[TOK*INNER];

// ---------------------------------------------------------------------------
// 1) LayerNorm: one block per token row (1024 elems), 256 threads
// ---------------------------------------------------------------------------
__global__ void __launch_bounds__(256) ln_kernel(const float* __restrict__ x,
                                                 const float* __restrict__ w,
                                                 const float* __restrict__ b,
                                                 float* __restrict__ xn) {
    const int row = blockIdx.x;
    const float* xr = x + (size_t)row * DIM;
    float v[4], s = 0.f, sq = 0.f;
#pragma unroll
    for (int i = 0; i < 4; i++) {
        v[i] = xr[threadIdx.x + i * 256];
        s  += v[i];
        sq += v[i] * v[i];
    }
    // warp reduce
#pragma unroll
    for (int off = 16; off; off >>= 1) {
        s  += __shfl_xor_sync(0xffffffffu, s, off);
        sq += __shfl_xor_sync(0xffffffffu, sq, off);
    }
    __shared__ float red[2][8];
    const int warp = threadIdx.x >> 5, lane = threadIdx.x & 31;
    if (lane == 0) { red[0][warp] = s; red[1][warp] = sq; }
    __syncthreads();
    float ts = 0.f, tq = 0.f;
#pragma unroll
    for (int i = 0; i < 8; i++) { ts += red[0][i]; tq += red[1][i]; }
    const float mean = ts * (1.0f / DIM);
    const float var  = tq * (1.0f / DIM) - mean * mean;
    const float rstd = rsqrtf(var + 1e-5f);
    float* xo = xn + (size_t)row * DIM;
#pragma unroll
    for (int i = 0; i < 4; i++) {
        const int c = threadIdx.x + i * 256;
        xo[c] = w[c] * (v[i] - mean) * rstd + b[c];
    }
}

// ---------------------------------------------------------------------------
// 2) SGEMM: C[M,N] = A[M,K] @ B[K,N], all row-major, dims multiples of 128
//    128x128 block tile, BK=8, 256 threads, 8x8 per-thread microtile
// ---------------------------------------------------------------------------
__global__ void __launch_bounds__(256) sgemm128(const float* __restrict__ A,
                                                const float* __restrict__ B,
                                                float* __restrict__ C,
                                                int M, int N, int K) {
    __shared__ float As[8][128];
    __shared__ float Bs[8][128];
    const int bm = blockIdx.y * 128;
    const int bn = blockIdx.x * 128;
    const int tid = threadIdx.x;

    const int arow = tid >> 1;            // 0..127
    const int acol = (tid & 1) << 2;      // 0 or 4
    const int brow = tid >> 5;            // 0..7
    const int bcol = (tid & 31) << 2;     // 0..124
    const float* Aptr = A + (size_t)(bm + arow) * K + acol;
    const float* Bptr = B + (size_t)brow * N + bn + bcol;

    const int ty = tid >> 4, tx = tid & 15;
    float c[8][8];
#pragma unroll
    for (int i = 0; i < 8; i++)
#pragma unroll
        for (int j = 0; j < 8; j++) c[i][j] = 0.f;

    for (int kt = 0; kt < K; kt += 8) {
        float4 a = *(const float4*)Aptr;  Aptr += 8;
        float4 bv = *(const float4*)Bptr; Bptr += (size_t)8 * N;
        As[acol + 0][arow] = a.x;
        As[acol + 1][arow] = a.y;
        As[acol + 2][arow] = a.z;
        As[acol + 3][arow] = a.w;
        *(float4*)&Bs[brow][bcol] = bv;
        __syncthreads();
#pragma unroll
        for (int k = 0; k < 8; k++) {
            float ar[8], br[8];
            *(float4*)(ar)     = *(const float4*)&As[k][ty * 4];
            *(float4*)(ar + 4) = *(const float4*)&As[k][64 + ty * 4];
            *(float4*)(br)     = *(const float4*)&Bs[k][tx * 4];
            *(float4*)(br + 4) = *(const float4*)&Bs[k][64 + tx * 4];
#pragma unroll
            for (int i = 0; i < 8; i++)
#pragma unroll
                for (int j = 0; j < 8; j++)
                    c[i][j] += ar[i] * br[j];
        }
        __syncthreads();
    }

#pragma unroll
    for (int ih = 0; ih < 2; ih++)
#pragma unroll
        for (int i = 0; i < 4; i++) {
            const int row = bm + ih * 64 + ty * 4 + i;
            float* cp = C + (size_t)row * N + bn + tx * 4;
            float4 v0 = make_float4(c[ih*4+i][0], c[ih*4+i][1], c[ih*4+i][2], c[ih*4+i][3]);
            float4 v1 = make_float4(c[ih*4+i][4], c[ih*4+i][5], c[ih*4+i][6], c[ih*4+i][7]);
            *(float4*)cp        = v0;
            *(float4*)(cp + 64) = v1;
        }
}

// ---------------------------------------------------------------------------
// 3) RMSNorm (q,k) + head split reshape. One block per token, warp per 2 heads.
// ---------------------------------------------------------------------------
__global__ void __launch_bounds__(256) rms_kernel(const float* __restrict__ q,
                                                  const float* __restrict__ kv,
                                                  const float* __restrict__ qg,
                                                  const float* __restrict__ kg,
                                                  float* __restrict__ qh,
                                                  float* __restrict__ kh,
                                                  float* __restrict__ vh) {
    const int token = blockIdx.x;
    const int b = token >> 11, s = token & 2047;
    const int warp = threadIdx.x >> 5, lane = threadIdx.x & 31;
#pragma unroll
    for (int i = 0; i < 2; i++) {
        const int h = warp * 2 + i;
        const size_t hidx = (((size_t)(b * Hn + h)) * Sq + s) * DHd;
        // q
        {
            const size_t qi = (size_t)token * INNER + h * DHd;
            float v0 = q[qi + lane], v1 = q[qi + lane + 32];
            float ss = v0 * v0 + v1 * v1;
#pragma unroll
            for (int off = 16; off; off >>= 1) ss += __shfl_xor_sync(0xffffffffu, ss, off);
            const float r = rsqrtf(ss * (1.0f / DHd) + 1e-8f) * 8.0f;
            qh[hidx + lane]      = v0 * r * qg[h * DHd + lane];
            qh[hidx + lane + 32] = v1 * r * qg[h * DHd + lane + 32];
        }
        // k and v
        {
            const size_t ki = (size_t)token * (2 * INNER) + h * DHd;
            float v0 = kv[ki + lane], v1 = kv[ki + lane + 32];
            float ss = v0 * v0 + v1 * v1;
#pragma unroll
            for (int off = 16; off; off >>= 1) ss += __shfl_xor_sync(0xffffffffu, ss, off);
            const float r = rsqrtf(ss * (1.0f / DHd) + 1e-8f) * 8.0f;
            kh[hidx + lane]      = v0 * r * kg[h * DHd + lane];
            kh[hidx + lane + 32] = v1 * r * kg[h * DHd + lane + 32];
            vh[hidx + lane]      = kv[ki + INNER + lane];
            vh[hidx + lane + 32] = kv[ki + INNER + lane + 32];
        }
    }
}

// ---------------------------------------------------------------------------
// 4) Attention: flash-style. Block = 64 Q rows of one (b,h); loops 32 KV tiles.
//    8 warps, warp owns 8 rows. Lane owns dims {2*lane, 2*lane+1} of O.
//    smem: Qs/Ks/Vs [64][68] (pad-68: conflict-free float4/float2), Ps [64][64]
// ---------------------------------------------------------------------------
#define ATT_SMEM ((3 * 64 * 68 + 64 * 64) * 4)

__global__ void __launch_bounds__(256) attn_kernel(const float* __restrict__ Qh,
                                                   const float* __restrict__ Kh,
                                                   const float* __restrict__ Vh,
                                                   float* __restrict__ Out) {
    extern __shared__ float sm[];
    float* Qs = sm;                // [64][68]
    float* Ks = sm + 64 * 68;      // [64][68]
    float* Vs = sm + 2 * 64 * 68;  // [64][68]
    float* Ps = sm + 3 * 64 * 68;  // [64][64]

    const int tid = threadIdx.x;
    const int warp = tid >> 5, lane = tid & 31;
    const int bh = blockIdx.y;
    const int b = bh >> 4, h = bh & 15;
    const int q0 = blockIdx.x * 64;
    const float* Qb = Qh + (size_t)bh * Sq * DHd;
    const float* Kb = Kh + (size_t)bh * Sq * DHd;
    const float* Vb = Vh + (size_t)bh * Sq * DHd;

    // load Q tile (64x64)
#pragma unroll
    for (int i = 0; i < 4; i++) {
        const int lin = tid + i * 256;       // float4 index 0..1023
        const int row = lin >> 4;
        const int c4  = (lin & 15) << 2;
        *(float4*)(Qs + row * 68 + c4) = *(const float4*)(Qb + (size_t)(q0 + row) * 64 + c4);
    }

    float m[8], l[8], a0[8], a1[8];
#pragma unroll
    for (int r = 0; r < 8; r++) { m[r] = -1e30f; l[r] = 0.f; a0[r] = 0.f; a1[r] = 0.f; }

    for (int t = 0; t < 32; t++) {
        __syncthreads();   // protect Ks/Vs/Ps reuse
        const int k0 = t * 64;
#pragma unroll
        for (int i = 0; i < 4; i++) {
            const int lin = tid + i * 256;
            const int row = lin >> 4;
            const int c4  = (lin & 15) << 2;
            *(float4*)(Ks + row * 68 + c4) = *(const float4*)(Kb + (size_t)(k0 + row) * 64 + c4);
            *(float4*)(Vs + row * 68 + c4) = *(const float4*)(Vb + (size_t)(k0 + row) * 64 + c4);
        }
        __syncthreads();

        // S = Q K^T : lane owns cols {lane, lane+32}, warp owns 8 rows
        float s0[8], s1[8];
#pragma unroll
        for (int r = 0; r < 8; r++) { s0[r] = 0.f; s1[r] = 0.f; }
#pragma unroll
        for (int d4 = 0; d4 < 16; d4++) {
            const float4 ka = *(const float4*)(Ks + lane * 68 + d4 * 4);
            const float4 kb = *(const float4*)(Ks + (lane + 32) * 68 + d4 * 4);
#pragma unroll
            for (int r = 0; r < 8; r++) {
                const float4 qv = *(const float4*)(Qs + (warp * 8 + r) * 68 + d4 * 4);
                s0[r] += qv.x * ka.x + qv.y * ka.y + qv.z * ka.z + qv.w * ka.w;
                s1[r] += qv.x * kb.x + qv.y * kb.y + qv.z * kb.z + qv.w * kb.w;
            }
        }

        // online softmax per row, P -> smem
#pragma unroll
        for (int r = 0; r < 8; r++) {
            float mx = fmaxf(s0[r], s1[r]);
#pragma unroll
            for (int off = 16; off; off >>= 1) mx = fmaxf(mx, __shfl_xor_sync(0xffffffffu, mx, off));
            const float mn = fmaxf(m[r], mx);
            const float corr = __expf(m[r] - mn);
            const float p0 = __expf(s0[r] - mn);
            const float p1 = __expf(s1[r] - mn);
            float ls = p0 + p1;
#pragma unroll
            for (int off = 16; off; off >>= 1) ls += __shfl_xor_sync(0xffffffffu, ls, off);
            l[r] = l[r] * corr + ls;
            a0[r] *= corr;
            a1[r] *= corr;
            m[r] = mn;
            Ps[(warp * 8 + r) * 64 + lane]      = p0;
            Ps[(warp * 8 + r) * 64 + lane + 32] = p1;
        }
        __syncwarp();

        // O += P V : lane owns dims {2*lane, 2*lane+1}
#pragma unroll
        for (int j4 = 0; j4 < 16; j4++) {
            const int j = j4 * 4;
            const float2 va = *(const float2*)(Vs + (j + 0) * 68 + 2 * lane);
            const float2 vb = *(const float2*)(Vs + (j + 1) * 68 + 2 * lane);
            const float2 vc = *(const float2*)(Vs + (j + 2) * 68 + 2 * lane);
            const float2 vd = *(const float2*)(Vs + (j + 3) * 68 + 2 * lane);
#pragma unroll
            for (int r = 0; r < 8; r++) {
                const float4 p = *(const float4*)(Ps + (warp * 8 + r) * 64 + j);
                a0[r] += p.x * va.x + p.y * vb.x + p.z * vc.x + p.w * vd.x;
                a1[r] += p.x * va.y + p.y * vb.y + p.z * vc.y + p.w * vd.y;
            }
        }
    }

    // epilogue: Out[b][s][h*64+d] = acc / l
#pragma unroll
    for (int r = 0; r < 8; r++) {
        const float inv = 1.0f / l[r];
        const int row = q0 + warp * 8 + r;
        float* o = Out + ((size_t)b * Sq + row) * INNER + h * DHd + 2 * lane;
        float2 v = make_float2(a0[r] * inv, a1[r] * inv);
        *(float2*)o = v;
    }
}

// ---------------------------------------------------------------------------
// Launcher
// ---------------------------------------------------------------------------
extern "C" void kernel_launch(void* const* d_in, const int* in_sizes, int n_in,
                              void* d_out, int out_size) {
    const float* x    = (const float*)d_in[0];
    const float* ln_w = (const float*)d_in[1];
    const float* ln_b = (const float*)d_in[2];
    const float* Wq   = (const float*)d_in[3];
    const float* Wkv  = (const float*)d_in[4];
    const float* qg   = (const float*)d_in[5];
    const float* kg   = (const float*)d_in[6];
    const float* Wo   = (const float*)d_in[7];
    float* out = (float*)d_out;

    float *xn, *q, *kv, *qh, *kh, *vh, *ao;
    cudaGetSymbolAddress((void**)&xn, g_xn);
    cudaGetSymbolAddress((void**)&q,  g_q);
    cudaGetSymbolAddress((void**)&kv, g_kv);
    cudaGetSymbolAddress((void**)&qh, g_qh);
    cudaGetSymbolAddress((void**)&kh, g_kh);
    cudaGetSymbolAddress((void**)&vh, g_vh);
    cudaGetSymbolAddress((void**)&ao, g_ao);

    ln_kernel<<<TOK, 256>>>(x, ln_w, ln_b, xn);
    sgemm128<<<dim3(INNER / 128, TOK / 128), 256>>>(xn, Wq, q, TOK, INNER, DIM);
    sgemm128<<<dim3(2 * INNER / 128, TOK / 128), 256>>>(xn, Wkv, kv, TOK, 2 * INNER, DIM);
    rms_kernel<<<TOK, 256>>>(q, kv, qg, kg, qh, kh, vh);

    cudaFuncSetAttribute(attn_kernel, cudaFuncAttributeMaxDynamicSharedMemorySize, ATT_SMEM);
    attn_kernel<<<dim3(Sq / 64, Bz * Hn), 256, ATT_SMEM>>>(qh, kh, vh, ao);

    sgemm128<<<dim3(DIM / 128, TOK / 128), 256>>>(ao, Wo, out, TOK, DIM, INNER);
}

// round 4
// speedup vs baseline: 2.7464x; 2.7464x over previous
#include <cuda_runtime.h>
#include <cuda_bf16.h>
#include <cstdint>

#define Bz    2
#define Sq    2048
#define DIM   1024
#define Hn    16
#define DHd   64
#define INNER 1024
#define TOK   4096

// ---------------------------------------------------------------------------
// Scratch (device globals). All fragment arrays are uint32 (packed bf16x2).
// ---------------------------------------------------------------------------
__device__ uint32_t g_xn_h[TOK*DIM/2],     g_xn_l[TOK*DIM/2];
__device__ uint32_t g_Wq_h[DIM*INNER/2],   g_Wq_l[DIM*INNER/2];
__device__ uint32_t g_Wkv_h[DIM*INNER],    g_Wkv_l[DIM*INNER];      // 2*INNER*DIM/2
__device__ uint32_t g_Wo_h[INNER*DIM/2],   g_Wo_l[INNER*DIM/2];
__device__ float    g_q [TOK*INNER];
__device__ float    g_kv[TOK*2*INNER];
__device__ uint32_t g_qf_h[TOK*INNER/2],   g_qf_l[TOK*INNER/2];
__device__ uint32_t g_kf_h[TOK*INNER/2],   g_kf_l[TOK*INNER/2];
__device__ uint32_t g_vf_h[TOK*INNER/2],   g_vf_l[TOK*INNER/2];
__device__ uint32_t g_ao_h[TOK*INNER/2],   g_ao_l[TOK*INNER/2];

// ---------------------------------------------------------------------------
// Helpers
// ---------------------------------------------------------------------------
__device__ __forceinline__ uint32_t smem_u32(const void* p) {
    uint32_t a;
    asm("{ .reg .u64 t; cvta.to.shared.u64 t, %1; cvt.u32.u64 %0, t; }" : "=r"(a) : "l"(p));
    return a;
}
__device__ __forceinline__ uint32_t pkbf(float a, float b) {
    return (uint32_t)__bfloat16_as_ushort(__float2bfloat16_rn(a)) |
           ((uint32_t)__bfloat16_as_ushort(__float2bfloat16_rn(b)) << 16);
}
__device__ __forceinline__ void splitbf(float a, float b, uint32_t& hi, uint32_t& lo) {
    __nv_bfloat16 ha = __float2bfloat16_rn(a), hb = __float2bfloat16_rn(b);
    hi = (uint32_t)__bfloat16_as_ushort(ha) | ((uint32_t)__bfloat16_as_ushort(hb) << 16);
    lo = pkbf(a - __bfloat162float(ha), b - __bfloat162float(hb));
}
__device__ __forceinline__ void mma_bf(float* c, const uint32_t* a, const uint32_t* b) {
    asm volatile(
        "mma.sync.aligned.m16n8k16.row.col.f32.bf16.bf16.f32 "
        "{%0,%1,%2,%3}, {%4,%5,%6,%7}, {%8,%9}, {%0,%1,%2,%3};"
        : "+f"(c[0]), "+f"(c[1]), "+f"(c[2]), "+f"(c[3])
        : "r"(a[0]), "r"(a[1]), "r"(a[2]), "r"(a[3]), "r"(b[0]), "r"(b[1]));
}
__device__ __forceinline__ void cpa16(uint32_t saddr, const void* gptr) {
    asm volatile("cp.async.cg.shared.global [%0], [%1], 16;" :: "r"(saddr), "l"(gptr) : "memory");
}
__device__ __forceinline__ void cp_commit() { asm volatile("cp.async.commit_group;" ::: "memory"); }
template <int N> __device__ __forceinline__ void cp_wait() {
    asm volatile("cp.async.wait_group %0;" :: "n"(N) : "memory");
}

// ---------------------------------------------------------------------------
// 1) LayerNorm -> A-fragment-major bf16 hi/lo
//    A-frag idx(row, pair p): mt=row>>4, g=(row&15)&7, hih=(row&15)>>3
//    ks=p>>3, c=p&7, tq=c&3, ch=c>>2 -> ((mt*K/16+ks)*128) + (g*4+tq)*4 + hih + 2*ch
// ---------------------------------------------------------------------------
__global__ void __launch_bounds__(256) ln_kernel(const float* __restrict__ x,
                                                 const float* __restrict__ w,
                                                 const float* __restrict__ bias,
                                                 uint32_t* __restrict__ xh,
                                                 uint32_t* __restrict__ xl) {
    const int row = blockIdx.x;
    const float* xr = x + (size_t)row * DIM;
    float2 v[2];
    v[0] = *(const float2*)(xr + 2 * threadIdx.x);
    v[1] = *(const float2*)(xr + 2 * (threadIdx.x + 256));
    float s  = v[0].x + v[0].y + v[1].x + v[1].y;
    float sq = v[0].x * v[0].x + v[0].y * v[0].y + v[1].x * v[1].x + v[1].y * v[1].y;
#pragma unroll
    for (int off = 16; off; off >>= 1) {
        s  += __shfl_xor_sync(0xffffffffu, s, off);
        sq += __shfl_xor_sync(0xffffffffu, sq, off);
    }
    __shared__ float red[2][8];
    const int warp = threadIdx.x >> 5, lane = threadIdx.x & 31;
    if (lane == 0) { red[0][warp] = s; red[1][warp] = sq; }
    __syncthreads();
    float ts = 0.f, tq2 = 0.f;
#pragma unroll
    for (int i = 0; i < 8; i++) { ts += red[0][i]; tq2 += red[1][i]; }
    const float mean = ts * (1.0f / DIM);
    const float var  = tq2 * (1.0f / DIM) - mean * mean;
    const float rstd = rsqrtf(var + 1e-5f);
    const int mt = row >> 4, mr = row & 15, g = mr & 7, hih = mr >> 3;
#pragma unroll
    for (int i = 0; i < 2; i++) {
        const int p = threadIdx.x + i * 256;
        const float2 wv = *(const float2*)(w + 2 * p);
        const float2 bv = *(const float2*)(bias + 2 * p);
        const float y0 = wv.x * (v[i].x - mean) * rstd + bv.x;
        const float y1 = wv.y * (v[i].y - mean) * rstd + bv.y;
        const int ks = p >> 3, c = p & 7, tq = c & 3, ch = c >> 2;
        const size_t idx = ((size_t)(mt * 64 + ks)) * 128 + (g * 4 + tq) * 4 + hih + 2 * ch;
        uint32_t hi, lo;
        splitbf(y0, y1, hi, lo);
        xh[idx] = hi; xl[idx] = lo;
    }
}

// ---------------------------------------------------------------------------
// 1b) Weight W[K,N] row-major -> B-fragment-major hi/lo
//    B-frag idx(pair p, n): nt=n>>3, g=n&7, ks=p>>3, c=p&7, tq=c&3, reg=c>>2
//    -> ((nt*(K/16)+ks)*64) + (g*4+tq)*2 + reg
// ---------------------------------------------------------------------------
__global__ void __launch_bounds__(256) wfrag(const float* __restrict__ W,
                                             uint32_t* __restrict__ oh,
                                             uint32_t* __restrict__ ol,
                                             int K, int lgN) {
    const int id = blockIdx.x * 256 + threadIdx.x;
    const int N = 1 << lgN;
    const int p = id >> lgN;
    const int n = id & (N - 1);
    const float a = W[(size_t)(2 * p) * N + n];
    const float b = W[(size_t)(2 * p + 1) * N + n];
    const int KS = K >> 4;
    const size_t idx = ((size_t)((n >> 3) * KS + (p >> 3))) * 64 + ((n & 7) * 4 + (p & 3)) * 2 + ((p >> 2) & 1);
    uint32_t hi, lo;
    splitbf(a, b, hi, lo);
    oh[idx] = hi; ol[idx] = lo;
}

// ---------------------------------------------------------------------------
// 2) bf16x3 GEMM: C[M,N] = A @ B, 128x128 tile, BK=32 (2 k-steps),
//    cp.async double-buffered, 256 thr = 8 warps (2x4), 3 MMAs per frag pair.
// ---------------------------------------------------------------------------
__global__ void __launch_bounds__(256) gemm_bf3(const uint32_t* __restrict__ Ah,
                                                const uint32_t* __restrict__ Al,
                                                const uint32_t* __restrict__ Bh,
                                                const uint32_t* __restrict__ Bl,
                                                float* __restrict__ C,
                                                int N, int K) {
    extern __shared__ uint32_t sm[];
    const int tid = threadIdx.x, wid = tid >> 5, lane = tid & 31;
    const int wr = wid >> 2, wc = wid & 3, g = lane >> 2, tq = lane & 3;
    const int bm = blockIdx.y * 128, bn = blockIdx.x * 128;
    const int KS = K >> 4, NSTG = K >> 5;
    const uint32_t sbase = smem_u32(sm);

    const uint32_t* Ah0 = Ah + (size_t)(bm >> 4) * KS * 128;
    const uint32_t* Al0 = Al + (size_t)(bm >> 4) * KS * 128;
    const uint32_t* Bh0 = Bh + (size_t)(bn >> 3) * KS * 64;
    const uint32_t* Bl0 = Bl + (size_t)(bn >> 3) * KS * 64;

    float acc[4][4][4];
#pragma unroll
    for (int i = 0; i < 4; i++)
#pragma unroll
        for (int j = 0; j < 4; j++)
#pragma unroll
            for (int e = 0; e < 4; e++) acc[i][j][e] = 0.f;

#define G_ISSUE(S, BUF) do {                                                        \
    const uint32_t sb_ = sbase + (BUF) * 32768u;                                    \
    _Pragma("unroll")                                                               \
    for (int i_ = 0; i_ < 2; i_++) {                                                \
        const int f_ = tid + i_ * 256;                                              \
        const int mt_ = f_ >> 6, wA_ = (4 * f_) & 255;                              \
        const int ksA_ = wA_ >> 7, frA_ = wA_ & 127;                                \
        const size_t oa_ = ((size_t)mt_ * KS + (S) * 2 + ksA_) * 128 + frA_;        \
        cpa16(sb_ + f_ * 16u,           Ah0 + oa_);                                 \
        cpa16(sb_ + 8192u + f_ * 16u,   Al0 + oa_);                                 \
        const int nt_ = f_ >> 5, wB_ = (4 * f_) & 127;                              \
        const int ksB_ = wB_ >> 6, frB_ = wB_ & 63;                                 \
        const size_t ob_ = ((size_t)nt_ * KS + (S) * 2 + ksB_) * 64 + frB_;         \
        cpa16(sb_ + 16384u + f_ * 16u,  Bh0 + ob_);                                 \
        cpa16(sb_ + 24576u + f_ * 16u,  Bl0 + ob_);                                 \
    }                                                                               \
    cp_commit();                                                                    \
} while (0)

    G_ISSUE(0, 0);
    int buf = 0;
    for (int s = 0; s < NSTG; s++) {
        if (s + 1 < NSTG) { G_ISSUE(s + 1, buf ^ 1); cp_wait<1>(); }
        else              { cp_wait<0>(); }
        __syncthreads();
        const uint32_t* S0 = sm + buf * 8192;
#pragma unroll
        for (int ksl = 0; ksl < 2; ksl++) {
            uint4 ah[4], al[4];
            uint2 bh[4], bl[4];
#pragma unroll
            for (int i = 0; i < 4; i++) {
                const int mt = wr * 4 + i;
                ah[i] = *(const uint4*)(S0 + (mt * 2 + ksl) * 128 + (g * 4 + tq) * 4);
                al[i] = *(const uint4*)(S0 + 2048 + (mt * 2 + ksl) * 128 + (g * 4 + tq) * 4);
            }
#pragma unroll
            for (int j = 0; j < 4; j++) {
                const int nt = wc * 4 + j;
                bh[j] = *(const uint2*)(S0 + 4096 + (nt * 2 + ksl) * 64 + (g * 4 + tq) * 2);
                bl[j] = *(const uint2*)(S0 + 6144 + (nt * 2 + ksl) * 64 + (g * 4 + tq) * 2);
            }
#pragma unroll
            for (int i = 0; i < 4; i++)
#pragma unroll
                for (int j = 0; j < 4; j++) {
                    mma_bf(acc[i][j], (const uint32_t*)&ah[i], (const uint32_t*)&bh[j]);
                    mma_bf(acc[i][j], (const uint32_t*)&ah[i], (const uint32_t*)&bl[j]);
                    mma_bf(acc[i][j], (const uint32_t*)&al[i], (const uint32_t*)&bh[j]);
                }
        }
        __syncthreads();
        buf ^= 1;
    }
#undef G_ISSUE

    // epilogue: row-major C
#pragma unroll
    for (int i = 0; i < 4; i++) {
        const int r0 = bm + (wr * 4 + i) * 16 + g;
#pragma unroll
        for (int j = 0; j < 4; j++) {
            const int c0 = bn + (wc * 4 + j) * 8 + 2 * tq;
            *(float2*)(C + (size_t)r0 * N + c0)       = make_float2(acc[i][j][0], acc[i][j][1]);
            *(float2*)(C + (size_t)(r0 + 8) * N + c0) = make_float2(acc[i][j][2], acc[i][j][3]);
        }
    }
}

// ---------------------------------------------------------------------------
// 3) RMSNorm + head-split, writing Q as A-frags and K, V as B-frags (hi/lo).
//    Block = 2 tokens (for V seq-pairing); warp handles 2 heads.
//    K layout per bh: ((bh*256+nt)*4+ks)*64+frag  (nt = s>>3, k = d)
//    V layout per bh: ((bh*128+ks)*8+nt)*64+frag  (k = seq, nt = d>>3)
//    Q layout per bh: ((bh*128+mt)*4+ks)*128+frag (mt = s>>4, k = d)
// ---------------------------------------------------------------------------
__global__ void __launch_bounds__(256) rms_kernel(const float* __restrict__ q,
                                                  const float* __restrict__ kv,
                                                  const float* __restrict__ qg,
                                                  const float* __restrict__ kg,
                                                  uint32_t* __restrict__ qfh, uint32_t* __restrict__ qfl,
                                                  uint32_t* __restrict__ kfh, uint32_t* __restrict__ kfl,
                                                  uint32_t* __restrict__ vfh, uint32_t* __restrict__ vfl) {
    const int tk0 = blockIdx.x * 2;
    const int warp = threadIdx.x >> 5, lane = threadIdx.x & 31;
    const int b = tk0 >> 11, s0 = tk0 & 2047;
    const int ks = lane >> 3, c = lane & 7, tq = c & 3, ch = c >> 2;
#pragma unroll
    for (int i = 0; i < 2; i++) {
        const int h = warp * 2 + i;
        const int bh = b * 16 + h;
        const float2 gq = *(const float2*)(qg + h * 64 + 2 * lane);
        const float2 gk = *(const float2*)(kg + h * 64 + 2 * lane);
#pragma unroll
        for (int tt = 0; tt < 2; tt++) {
            const int token = tk0 + tt, s = s0 + tt;
            // q
            {
                const float2 qv = *(const float2*)(q + (size_t)token * INNER + h * 64 + 2 * lane);
                float ss = qv.x * qv.x + qv.y * qv.y;
#pragma unroll
                for (int off = 16; off; off >>= 1) ss += __shfl_xor_sync(0xffffffffu, ss, off);
                const float r = rsqrtf(ss * (1.0f / DHd) + 1e-8f) * 8.0f;
                const int mt = s >> 4, mr = s & 15, gg = mr & 7, hih = mr >> 3;
                const size_t qi = ((size_t)(bh * 128 + mt) * 4 + ks) * 128 + (gg * 4 + tq) * 4 + hih + 2 * ch;
                uint32_t hi, lo;
                splitbf(qv.x * r * gq.x, qv.y * r * gq.y, hi, lo);
                qfh[qi] = hi; qfl[qi] = lo;
            }
            // k
            {
                const float2 kvv = *(const float2*)(kv + (size_t)token * (2 * INNER) + h * 64 + 2 * lane);
                float ss = kvv.x * kvv.x + kvv.y * kvv.y;
#pragma unroll
                for (int off = 16; off; off >>= 1) ss += __shfl_xor_sync(0xffffffffu, ss, off);
                const float r = rsqrtf(ss * (1.0f / DHd) + 1e-8f) * 8.0f;
                const int nt = s >> 3, gg = s & 7;
                const size_t ki = ((size_t)(bh * 256 + nt) * 4 + ks) * 64 + (gg * 4 + tq) * 2 + ch;
                uint32_t hi, lo;
                splitbf(kvv.x * r * gk.x, kvv.y * r * gk.y, hi, lo);
                kfh[ki] = hi; kfl[ki] = lo;
            }
        }
        // v (pairs along seq: tokens tk0, tk0+1)
        {
            const float2 va = *(const float2*)(kv + (size_t)tk0 * (2 * INNER) + INNER + h * 64 + 2 * lane);
            const float2 vb = *(const float2*)(kv + (size_t)(tk0 + 1) * (2 * INNER) + INNER + h * 64 + 2 * lane);
            const int pq = s0 >> 1;
            const int ksv = pq >> 3, cv = pq & 7, tv = cv & 3, rv = cv >> 2;
            const int d0 = 2 * lane;
            const size_t vi0 = ((size_t)(bh * 128 + ksv) * 8 + (d0 >> 3)) * 64 + ((d0 & 7) * 4 + tv) * 2 + rv;
            const size_t vi1 = ((size_t)(bh * 128 + ksv) * 8 + ((d0 + 1) >> 3)) * 64 + (((d0 + 1) & 7) * 4 + tv) * 2 + rv;
            uint32_t hi, lo;
            splitbf(va.x, vb.x, hi, lo); vfh[vi0] = hi; vfl[vi0] = lo;
            splitbf(va.y, vb.y, hi, lo); vfh[vi1] = hi; vfl[vi1] = lo;
        }
    }
}

// ---------------------------------------------------------------------------
// 4) Flash attention, bf16x3 MMA. CTA = 128 Q rows of one (b,h), 8 warps,
//    warp = 16 rows. Q frags in regs; K/V tiles (64 kv) cp.async double-buffered.
// ---------------------------------------------------------------------------
__global__ void __launch_bounds__(256) attn_bf(const uint32_t* __restrict__ Qh,
                                               const uint32_t* __restrict__ Ql,
                                               const uint32_t* __restrict__ Kh,
                                               const uint32_t* __restrict__ Kl,
                                               const uint32_t* __restrict__ Vh,
                                               const uint32_t* __restrict__ Vl,
                                               uint32_t* __restrict__ Oh,
                                               uint32_t* __restrict__ Ol) {
    extern __shared__ uint32_t sm[];
    const int tid = threadIdx.x, warp = tid >> 5, lane = tid & 31;
    const int g = lane >> 2, tq = lane & 3;
    const int bh = blockIdx.y, h = bh & 15;
    const int q0 = blockIdx.x * 128;
    const uint32_t sbase = smem_u32(sm);

    // Q fragments (resident)
    uint4 qh_[4], ql_[4];
    {
        const size_t qb = ((size_t)(bh * 128 + (q0 >> 4) + warp)) * 4;
#pragma unroll
        for (int ks = 0; ks < 4; ks++) {
            qh_[ks] = *(const uint4*)(Qh + (qb + ks) * 128 + (g * 4 + tq) * 4);
            ql_[ks] = *(const uint4*)(Ql + (qb + ks) * 128 + (g * 4 + tq) * 4);
        }
    }

    const uint32_t* Kh0 = Kh + (size_t)bh * 65536;
    const uint32_t* Kl0 = Kl + (size_t)bh * 65536;
    const uint32_t* Vh0 = Vh + (size_t)bh * 65536;
    const uint32_t* Vl0 = Vl + (size_t)bh * 65536;

    float oacc[8][4];
#pragma unroll
    for (int j = 0; j < 8; j++)
#pragma unroll
        for (int e = 0; e < 4; e++) oacc[j][e] = 0.f;
    float m0 = -1e30f, m1 = -1e30f, l0 = 0.f, l1 = 0.f;

#define A_ISSUE(T, BUF) do {                                                  \
    const uint32_t sb_ = sbase + (BUF) * 32768u;                              \
    _Pragma("unroll")                                                         \
    for (int i_ = 0; i_ < 2; i_++) {                                          \
        const int f_ = tid + i_ * 256;                                        \
        const size_t o_ = (size_t)(T) * 2048 + 4 * f_;                        \
        cpa16(sb_ + f_ * 16u,          Kh0 + o_);                             \
        cpa16(sb_ + 8192u + f_ * 16u,  Kl0 + o_);                             \
        cpa16(sb_ + 16384u + f_ * 16u, Vh0 + o_);                             \
        cpa16(sb_ + 24576u + f_ * 16u, Vl0 + o_);                             \
    }                                                                         \
    cp_commit();                                                              \
} while (0)

    A_ISSUE(0, 0);
    int buf = 0;
    for (int t = 0; t < Sq / 64; t++) {
        if (t + 1 < Sq / 64) { A_ISSUE(t + 1, buf ^ 1); cp_wait<1>(); }
        else                 { cp_wait<0>(); }
        __syncthreads();
        const uint32_t* SKh = sm + buf * 8192;
        const uint32_t* SKl = SKh + 2048;
        const uint32_t* SVh = SKh + 4096;
        const uint32_t* SVl = SKh + 6144;

        // S = Q K^T
        float sacc[8][4];
#pragma unroll
        for (int j = 0; j < 8; j++)
#pragma unroll
            for (int e = 0; e < 4; e++) sacc[j][e] = 0.f;
#pragma unroll
        for (int ks = 0; ks < 4; ks++) {
#pragma unroll
            for (int j = 0; j < 8; j++) {
                const uint2 kbh = *(const uint2*)(SKh + (j * 4 + ks) * 64 + (g * 4 + tq) * 2);
                const uint2 kbl = *(const uint2*)(SKl + (j * 4 + ks) * 64 + (g * 4 + tq) * 2);
                mma_bf(sacc[j], (const uint32_t*)&qh_[ks], (const uint32_t*)&kbh);
                mma_bf(sacc[j], (const uint32_t*)&qh_[ks], (const uint32_t*)&kbl);
                mma_bf(sacc[j], (const uint32_t*)&ql_[ks], (const uint32_t*)&kbh);
            }
        }

        // online softmax (rows g and g+8; quad lanes share a row)
        float mx0 = -1e30f, mx1 = -1e30f;
#pragma unroll
        for (int j = 0; j < 8; j++) {
            mx0 = fmaxf(mx0, fmaxf(sacc[j][0], sacc[j][1]));
            mx1 = fmaxf(mx1, fmaxf(sacc[j][2], sacc[j][3]));
        }
        mx0 = fmaxf(mx0, __shfl_xor_sync(0xffffffffu, mx0, 1));
        mx0 = fmaxf(mx0, __shfl_xor_sync(0xffffffffu, mx0, 2));
        mx1 = fmaxf(mx1, __shfl_xor_sync(0xffffffffu, mx1, 1));
        mx1 = fmaxf(mx1, __shfl_xor_sync(0xffffffffu, mx1, 2));
        const float nm0 = fmaxf(m0, mx0), nm1 = fmaxf(m1, mx1);
        const float c0 = __expf(m0 - nm0), c1 = __expf(m1 - nm1);
        float ls0 = 0.f, ls1 = 0.f;
#pragma unroll
        for (int j = 0; j < 8; j++) {
            sacc[j][0] = __expf(sacc[j][0] - nm0);
            sacc[j][1] = __expf(sacc[j][1] - nm0);
            sacc[j][2] = __expf(sacc[j][2] - nm1);
            sacc[j][3] = __expf(sacc[j][3] - nm1);
            ls0 += sacc[j][0] + sacc[j][1];
            ls1 += sacc[j][2] + sacc[j][3];
        }
        ls0 += __shfl_xor_sync(0xffffffffu, ls0, 1);
        ls0 += __shfl_xor_sync(0xffffffffu, ls0, 2);
        ls1 += __shfl_xor_sync(0xffffffffu, ls1, 1);
        ls1 += __shfl_xor_sync(0xffffffffu, ls1, 2);
        l0 = l0 * c0 + ls0; l1 = l1 * c1 + ls1;
        m0 = nm0; m1 = nm1;
#pragma unroll
        for (int j = 0; j < 8; j++) {
            oacc[j][0] *= c0; oacc[j][1] *= c0;
            oacc[j][2] *= c1; oacc[j][3] *= c1;
        }

        // P -> A-fragments (register-only)
        uint32_t pah[4][4], pal[4][4];
#pragma unroll
        for (int k2 = 0; k2 < 4; k2++) {
            splitbf(sacc[2 * k2][0],     sacc[2 * k2][1],     pah[k2][0], pal[k2][0]);
            splitbf(sacc[2 * k2][2],     sacc[2 * k2][3],     pah[k2][1], pal[k2][1]);
            splitbf(sacc[2 * k2 + 1][0], sacc[2 * k2 + 1][1], pah[k2][2], pal[k2][2]);
            splitbf(sacc[2 * k2 + 1][2], sacc[2 * k2 + 1][3], pah[k2][3], pal[k2][3]);
        }

        // O += P V
#pragma unroll
        for (int ks = 0; ks < 4; ks++) {
#pragma unroll
            for (int j = 0; j < 8; j++) {
                const uint2 vbh = *(const uint2*)(SVh + (ks * 8 + j) * 64 + (g * 4 + tq) * 2);
                const uint2 vbl = *(const uint2*)(SVl + (ks * 8 + j) * 64 + (g * 4 + tq) * 2);
                mma_bf(oacc[j], pah[ks], (const uint32_t*)&vbh);
                mma_bf(oacc[j], pah[ks], (const uint32_t*)&vbl);
                mma_bf(oacc[j], pal[ks], (const uint32_t*)&vbh);
            }
        }
        __syncthreads();
        buf ^= 1;
    }
#undef A_ISSUE

    // epilogue: O /= l, write A-fragment-major for output GEMM (K=INNER)
    const float inv0 = 1.0f / l0, inv1 = 1.0f / l1;
    const int mt_o = (bh >> 4) * 128 + (q0 >> 4) + warp;
#pragma unroll
    for (int j = 0; j < 8; j++) {
        const size_t ix0 = ((size_t)(mt_o * 64 + h * 4 + (j >> 1))) * 128 + (g * 4 + tq) * 4 + 2 * (j & 1);
        uint32_t hi, lo;
        splitbf(oacc[j][0] * inv0, oacc[j][1] * inv0, hi, lo);
        Oh[ix0] = hi; Ol[ix0] = lo;
        splitbf(oacc[j][2] * inv1, oacc[j][3] * inv1, hi, lo);
        Oh[ix0 + 1] = hi; Ol[ix0 + 1] = lo;
    }
}

// ---------------------------------------------------------------------------
// Launcher
// ---------------------------------------------------------------------------
#define SMEM_64K 65536

extern "C" void kernel_launch(void* const* d_in, const int* in_sizes, int n_in,
                              void* d_out, int out_size) {
    const float* x    = (const float*)d_in[0];
    const float* ln_w = (const float*)d_in[1];
    const float* ln_b = (const float*)d_in[2];
    const float* Wq   = (const float*)d_in[3];
    const float* Wkv  = (const float*)d_in[4];
    const float* qg   = (const float*)d_in[5];
    const float* kg   = (const float*)d_in[6];
    const float* Wo   = (const float*)d_in[7];
    float* out = (float*)d_out;

    uint32_t *xnh, *xnl, *wqh, *wql, *wkvh, *wkvl, *woh, *wol;
    uint32_t *qfh, *qfl, *kfh, *kfl, *vfh, *vfl, *aoh, *aol;
    float *q, *kv;
    cudaGetSymbolAddress((void**)&xnh,  g_xn_h);  cudaGetSymbolAddress((void**)&xnl,  g_xn_l);
    cudaGetSymbolAddress((void**)&wqh,  g_Wq_h);  cudaGetSymbolAddress((void**)&wql,  g_Wq_l);
    cudaGetSymbolAddress((void**)&wkvh, g_Wkv_h); cudaGetSymbolAddress((void**)&wkvl, g_Wkv_l);
    cudaGetSymbolAddress((void**)&woh,  g_Wo_h);  cudaGetSymbolAddress((void**)&wol,  g_Wo_l);
    cudaGetSymbolAddress((void**)&qfh,  g_qf_h);  cudaGetSymbolAddress((void**)&qfl,  g_qf_l);
    cudaGetSymbolAddress((void**)&kfh,  g_kf_h);  cudaGetSymbolAddress((void**)&kfl,  g_kf_l);
    cudaGetSymbolAddress((void**)&vfh,  g_vf_h);  cudaGetSymbolAddress((void**)&vfl,  g_vf_l);
    cudaGetSymbolAddress((void**)&aoh,  g_ao_h);  cudaGetSymbolAddress((void**)&aol,  g_ao_l);
    cudaGetSymbolAddress((void**)&q,    g_q);     cudaGetSymbolAddress((void**)&kv,   g_kv);

    cudaFuncSetAttribute(gemm_bf3, cudaFuncAttributeMaxDynamicSharedMemorySize, SMEM_64K);
    cudaFuncSetAttribute(attn_bf,  cudaFuncAttributeMaxDynamicSharedMemorySize, SMEM_64K);

    ln_kernel<<<TOK, 256>>>(x, ln_w, ln_b, xnh, xnl);
    wfrag<<<(DIM / 2) * INNER / 256, 256>>>(Wq, wqh, wql, DIM, 10);
    wfrag<<<(DIM / 2) * (2 * INNER) / 256, 256>>>(Wkv, wkvh, wkvl, DIM, 11);
    wfrag<<<(INNER / 2) * DIM / 256, 256>>>(Wo, woh, wol, INNER, 10);

    gemm_bf3<<<dim3(INNER / 128, TOK / 128), 256, SMEM_64K>>>(xnh, xnl, wqh, wql, q, INNER, DIM);
    gemm_bf3<<<dim3(2 * INNER / 128, TOK / 128), 256, SMEM_64K>>>(xnh, xnl, wkvh, wkvl, kv, 2 * INNER, DIM);

    rms_kernel<<<TOK / 2, 256>>>(q, kv, qg, kg, qfh, qfl, kfh, kfl, vfh, vfl);

    attn_bf<<<dim3(Sq / 128, Bz * Hn), 256, SMEM_64K>>>(qfh, qfl, kfh, kfl, vfh, vfl, aoh, aol);

    gemm_bf3<<<dim3(DIM / 128, TOK / 128), 256, SMEM_64K>>>(aoh, aol, woh, wol, out, DIM, INNER);
}